// round 16
// baseline (speedup 1.0000x reference)
#include <cuda_runtime.h>
#include <cstdint>

#define HID   100
#define GXS   512
#define TENC  4096
#define TDEC  4096
#define NCLS  6
#define NTH   384          // 12 warps, 3/SMSP -> reg cap 170
#define LOG2E 1.4426950408889634f

typedef unsigned long long ull;

// per-step input contributions:
//  units 0-95:  slot = 32*(u>>3) + ((u&7)<<2) + gt   (== owning tid)
//  units 96-99: slot = 384 + (u-96)*4 + gt
__device__ float g_gge[TENC * GXS];
__device__ float g_ggd[TDEC * GXS];

// ---- packed f32x2 / math helpers ----
__device__ __forceinline__ ull fma2(ull a, ull b, ull c) {
    ull d;
    asm("fma.rn.f32x2 %0, %1, %2, %3;" : "=l"(d) : "l"(a), "l"(b), "l"(c));
    return d;
}
__device__ __forceinline__ ull add2(ull a, ull b) {
    ull d;
    asm("add.rn.f32x2 %0, %1, %2;" : "=l"(d) : "l"(a), "l"(b));
    return d;
}
__device__ __forceinline__ float ex2f(float x) {
    float y; asm("ex2.approx.f32 %0, %1;" : "=f"(y) : "f"(x)); return y;
}
__device__ __forceinline__ float rcpf(float x) {
    float y; asm("rcp.approx.f32 %0, %1;" : "=f"(y) : "f"(x)); return y;
}
__device__ __forceinline__ float tanhf_fast(float x) {
    return 1.0f - 2.0f * rcpf(1.0f + ex2f((2.0f * LOG2E) * x));
}
__device__ __forceinline__ float hsum2(ull s) {
    float lo, hi;
    asm("mov.b64 {%0,%1},%2;" : "=f"(lo), "=f"(hi) : "l"(s));
    return lo + hi;
}
// act = sigmoid (aa=0) or tanh (aa=1), branchless
__device__ __forceinline__ float gact(float d, float aa) {
    const float bb = fmaf(-3.0f, aa, 1.0f);
    const float kk = LOG2E * fmaf(3.0f, aa, -1.0f);
    return fmaf(bb, rcpf(1.0f + ex2f(kk * d)), aa);
}

// one 100-col row dot, 3-deep pipelined LDS.128, 2 accumulators, gx in acc init
__device__ __forceinline__ float dotsingle(const ull (&w)[50], unsigned hb, float gx) {
    ull bx[3], by[3];
#pragma unroll
    for (int m = 0; m < 3; ++m)
        asm volatile("ld.shared.v2.b64 {%0,%1},[%2];"
                     : "=l"(bx[m]), "=l"(by[m]) : "r"(hb + 16u * m));
    ull a0, a1 = 0ull;
    asm("mov.b64 %0,{%1,%2};" : "=l"(a0) : "f"(gx), "f"(0.0f));
#pragma unroll
    for (int m = 0; m < 25; ++m) {
        const int sl = m % 3;
        a0 = fma2(w[2 * m],     bx[sl], a0);
        a1 = fma2(w[2 * m + 1], by[sl], a1);
        if (m + 3 < 25)
            asm volatile("ld.shared.v2.b64 {%0,%1},[%2];"
                         : "=l"(bx[sl]), "=l"(by[sl]) : "r"(hb + 16u * (m + 3)));
    }
    return hsum2(add2(a0, a1));
}

// half-row dot from shared weights (w11 lanes): 13 iters, 26 FFMA2
__device__ __forceinline__ float dot_half(const float2* __restrict__ wq,
                                          const float* __restrict__ hbase) {
    ull a0 = 0ull, a1 = 0ull;
    const ulonglong2* wp = (const ulonglong2*)wq;
    const ulonglong2* hp = (const ulonglong2*)hbase;
#pragma unroll
    for (int k = 0; k < 13; ++k) {
        const ulonglong2 wv = wp[k];
        const ulonglong2 hv = hp[k];
        a0 = fma2(wv.x, hv.x, a0);
        a1 = fma2(wv.y, hv.y, a1);
    }
    return hsum2(add2(a0, a1));
}

// ---------------- prep kernel ----------------
__global__ void gx_prep_kernel(const float* __restrict__ x,
                               const int*   __restrict__ y,
                               const float* __restrict__ eWih,
                               const float* __restrict__ ebih,
                               const float* __restrict__ ebhh,
                               const float* __restrict__ dWih,
                               const float* __restrict__ dbih,
                               const float* __restrict__ dbhh)
{
    int idx = blockIdx.x * blockDim.x + threadIdx.x;
    if (idx >= TENC * 400) return;
    int t = idx / 400;
    int r = idx - t * 400;
    int u = r % 100, gt = r / 100;
    int slot = (u < 96) ? (32 * (u >> 3) + ((u & 7) << 2) + gt)
                        : (384 + (u - 96) * 4 + gt);
    int dst = t * GXS + slot;
    g_gge[dst] = ebih[r] + ebhh[r]
               + x[3*t+0] * eWih[3*r+0]
               + x[3*t+1] * eWih[3*r+1]
               + x[3*t+2] * eWih[3*r+2];
    g_ggd[dst] = dbih[r] + dbhh[r] + (float)y[t] * dWih[r];
}

__device__ __forceinline__ void logits_body(
    const float* __restrict__ hRead,
    const float* __restrict__ slw, const float* __restrict__ slb,
    float* __restrict__ out, int orow, int lane)
{
    const int cls = lane & 7, piece = lane >> 3;
    float acc = 0.0f;
    const float* lp = slw + cls * HID + piece * 25;    // cls 6,7 hit zero pad
    const float* hq = hRead + piece * 25;
#pragma unroll
    for (int k = 0; k < 25; ++k)
        acc = fmaf(lp[k], hq[k], acc);
    acc += __shfl_xor_sync(0xffffffffu, acc, 8);
    acc += __shfl_xor_sync(0xffffffffu, acc, 16);
    if (piece == 0 && cls < NCLS)
        out[orow * NCLS + cls] = acc + slb[cls];
}

// fill w11's shared half-row weight table for units 96-99 (called per phase)
__device__ __forceinline__ void fill_swq(float2 (*swq)[26],
                                         const float* __restrict__ Whh, int tid)
{
    for (int idx = tid; idx < 32 * 26; idx += NTH) {
        const int L = idx / 26, k = idx - L * 26;
        const int hf = L & 1, ri = L >> 1;
        const int u = 96 + (ri >> 2), gt = ri & 3;
        const float* row = Whh + (u + gt * HID) * HID;
        float v0 = 0.0f, v1 = 0.0f;
        if (hf == 0) {
            if (k < 24) { v0 = row[2 * k]; v1 = row[2 * k + 1]; }   // cols 0-47
        } else {
            v0 = row[48 + 2 * k]; v1 = row[49 + 2 * k];             // cols 48-99
        }
        swq[L][k] = make_float2(v0, v1);
    }
}

// one LSTM step for all 384 lanes
template<bool DEC>
__device__ __forceinline__ void step(
    int s, int TW, const float* __restrict__ gg,
    const ull (&w)[50], unsigned hbR, const float* __restrict__ hRf,
    float* __restrict__ hW,
    float& gx, float& gx2, float& c, float& c2, float aa, float aa2,
    int tid, int wid, int lane, int u,
    const float2 (*swq)[26],
    const float* __restrict__ slw, const float* __restrict__ slb,
    float* __restrict__ out)
{
    int sn = s + 1; if (sn > TW - 1) sn = TW - 1;
    const float nx = __ldg(gg + sn * GXS + tid);           // prefetch (hidden)
    float nx2 = 0.0f;
    if (wid == 11) nx2 = __ldg(gg + sn * GXS + 384 + (lane >> 1));

    const float d = dotsingle(w, hbR, gx);

    // full-row update (units 0-95)
    const float act = gact(d, aa);
    const int base = lane & ~3;
    const float iv = __shfl_sync(0xffffffffu, act, base);
    const float fv = __shfl_sync(0xffffffffu, act, base + 1);
    const float gv = __shfl_sync(0xffffffffu, act, base + 2);
    const float ov = __shfl_sync(0xffffffffu, act, base + 3);
    c = fmaf(fv, c, iv * gv);
    const float h = ov * tanhf_fast(c);
    if ((lane & 3) == 0) hW[u] = h;

    if (wid == 11) {
        // half-rows of units 96-99 (weights from shared swq)
        const int hf = lane & 1;
        float e = dot_half(swq[lane], hRf + hf * 48);
        e += __shfl_xor_sync(0xffffffffu, e, 1);
        e += gx2;
        const float act2 = gact(e, aa2);
        const int b2 = lane & ~7;                          // gates at b2+{0,2,4,6}
        const float i2 = __shfl_sync(0xffffffffu, act2, b2);
        const float f2 = __shfl_sync(0xffffffffu, act2, b2 + 2);
        const float g2 = __shfl_sync(0xffffffffu, act2, b2 + 4);
        const float o2 = __shfl_sync(0xffffffffu, act2, b2 + 6);
        c2 = fmaf(f2, c2, i2 * g2);
        const float h2 = o2 * tanhf_fast(c2);
        if ((lane & 7) == 0) hW[96 + (lane >> 3)] = h2;
        gx2 = nx2;
    } else if (DEC && wid == 10 && s >= 1) {
        logits_body(hRf, slw, slb, out, s - 1, lane);      // lagged logits
    }
    gx = nx;
}

// ---------------- persistent recurrence kernel ----------------
__global__ void __launch_bounds__(NTH, 1)
lstm_encdec_kernel(const float* __restrict__ eWhh,   // [400,100]
                   const float* __restrict__ dWhh,   // [400,100]
                   const float* __restrict__ linW,   // [6,100]
                   const float* __restrict__ linb,   // [6]
                   float* __restrict__ out)          // [TDEC,6]
{
    __shared__ __align__(1024) float hbuf[2][128];
    __shared__ __align__(16) float2 swq[32][26];     // w11 half-row weights
    __shared__ float slw[8 * HID];
    __shared__ float slb[NCLS];

    const int tid  = threadIdx.x;
    const int wid  = tid >> 5;
    const int lane = tid & 31;
    const int u    = 8 * wid + (lane >> 2);          // 0..95
    const int gt   = lane & 3;

    // ---- init ----
    if (tid < 128) { hbuf[0][tid] = 0.0f; hbuf[1][tid] = 0.0f; }
    if (tid < NCLS) { out[(TDEC - 1) * NCLS + tid] = 0.0f; slb[tid] = linb[tid]; }
    for (int i = tid; i < 8 * HID; i += NTH)
        slw[i] = (i < NCLS * HID) ? linW[i] : 0.0f;

    const float aa  = (gt == 2) ? 1.0f : 0.0f;
    const float aa2 = (((lane >> 1) & 3) == 2) ? 1.0f : 0.0f;   // w11 extra gate

    // ---- encoder weights ----
    ull w[50];
    {
        const ull* p = (const ull*)(eWhh + (u + gt * HID) * HID);
#pragma unroll
        for (int k = 0; k < 50; ++k) w[k] = p[k];
    }
    fill_swq(swq, eWhh, tid);
    float c = 0.0f, c2 = 0.0f;
    __syncthreads();

    const unsigned hb0 = (unsigned)__cvta_generic_to_shared(&hbuf[0][0]);
    const unsigned hb1 = hb0 + 512u;
    float* const h0 = &hbuf[0][0];
    float* const h1 = &hbuf[1][0];

    float gx  = __ldg(g_gge + tid);
    float gx2 = (wid == 11) ? __ldg(g_gge + 384 + (lane >> 1)) : 0.0f;

    // ================= encoder: 4096 steps =================
#pragma unroll 1
    for (int it = 0; it < TENC / 2; ++it) {
        step<false>(2*it,     TENC, g_gge, w, hb0, h0, h1, gx, gx2, c, c2,
                    aa, aa2, tid, wid, lane, u, swq, slw, slb, out);
        __syncthreads();
        step<false>(2*it + 1, TENC, g_gge, w, hb1, h1, h0, gx, gx2, c, c2,
                    aa, aa2, tid, wid, lane, u, swq, slw, slb, out);
        __syncthreads();
    }
    // h_enc in hbuf[0]

    // ---- decoder weights ----
    {
        const ull* p = (const ull*)(dWhh + (u + gt * HID) * HID);
#pragma unroll
        for (int k = 0; k < 50; ++k) w[k] = p[k];
    }
    fill_swq(swq, dWhh, tid);                // prev barrier covers old readers
    gx  = __ldg(g_ggd + tid);
    gx2 = (wid == 11) ? __ldg(g_ggd + 384 + (lane >> 1)) : 0.0f;
    __syncthreads();                         // swq visible before first use

    // ================= decoder: 4095 work steps =================
    const int TW = TDEC - 1;                 // 4095
#pragma unroll 1
    for (int it = 0; it < (TW - 1) / 2; ++it) {       // steps 0..4093
        step<true>(2*it,     TW, g_ggd, w, hb0, h0, h1, gx, gx2, c, c2,
                   aa, aa2, tid, wid, lane, u, swq, slw, slb, out);
        __syncthreads();
        step<true>(2*it + 1, TW, g_ggd, w, hb1, h1, h0, gx, gx2, c, c2,
                   aa, aa2, tid, wid, lane, u, swq, slw, slb, out);
        __syncthreads();
    }
    // final work step 4094 (reads h0, writes h1); logits row 4093 inside
    step<true>(TW - 1, TW, g_ggd, w, hb0, h0, h1, gx, gx2, c, c2,
               aa, aa2, tid, wid, lane, u, swq, slw, slb, out);
    __syncthreads();
    // logits row 4094 from h1 = final h (row 4095 stays zero)
    if (wid == 10) logits_body(h1, slw, slb, out, TDEC - 2, lane);
}

extern "C" void kernel_launch(void* const* d_in, const int* in_sizes, int n_in,
                              void* d_out, int out_size) {
    const float* x     = (const float*)d_in[0];
    const int*   y     = (const int*)  d_in[1];
    const float* eWih  = (const float*)d_in[2];
    const float* eWhh  = (const float*)d_in[3];
    const float* ebih  = (const float*)d_in[4];
    const float* ebhh  = (const float*)d_in[5];
    const float* dWih  = (const float*)d_in[6];
    const float* dWhh  = (const float*)d_in[7];
    const float* dbih  = (const float*)d_in[8];
    const float* dbhh  = (const float*)d_in[9];
    const float* linW  = (const float*)d_in[10];
    const float* linb  = (const float*)d_in[11];
    float* out = (float*)d_out;

    const int n = TENC * 400;
    gx_prep_kernel<<<(n + 255) / 256, 256>>>(x, y, eWih, ebih, ebhh,
                                             dWih, dbih, dbhh);
    lstm_encdec_kernel<<<1, NTH>>>(eWhh, dWhh, linW, linb, out);
}

// round 17
// speedup vs baseline: 1.0631x; 1.0631x over previous
#include <cuda_runtime.h>
#include <cstdint>

#define HID   100
#define GXS   512
#define TENC  4096
#define TDEC  4096
#define NCLS  6
#define NTH   384          // 12 warps, 3/SMSP -> reg cap 170
#define LOG2E 1.4426950408889634f

typedef unsigned long long ull;

// per-step input contributions:
//  units 0-95:  slot = 32*(u>>3) + ((u&7)<<2) + gt   (== owning tid)
//  units 96-99: slot = 384 + (u-96)*4 + gt
__device__ float g_gge[TENC * GXS];
__device__ float g_ggd[TDEC * GXS];

// ---- packed f32x2 / math helpers ----
__device__ __forceinline__ ull fma2(ull a, ull b, ull c) {
    ull d;
    asm("fma.rn.f32x2 %0, %1, %2, %3;" : "=l"(d) : "l"(a), "l"(b), "l"(c));
    return d;
}
__device__ __forceinline__ ull add2(ull a, ull b) {
    ull d;
    asm("add.rn.f32x2 %0, %1, %2;" : "=l"(d) : "l"(a), "l"(b));
    return d;
}
__device__ __forceinline__ float ex2f(float x) {
    float y; asm("ex2.approx.f32 %0, %1;" : "=f"(y) : "f"(x)); return y;
}
__device__ __forceinline__ float rcpf(float x) {
    float y; asm("rcp.approx.f32 %0, %1;" : "=f"(y) : "f"(x)); return y;
}
__device__ __forceinline__ float tanhf_fast(float x) {
    return 1.0f - 2.0f * rcpf(1.0f + ex2f((2.0f * LOG2E) * x));
}
__device__ __forceinline__ float hsum2(ull s) {
    float lo, hi;
    asm("mov.b64 {%0,%1},%2;" : "=f"(lo), "=f"(hi) : "l"(s));
    return lo + hi;
}
// act = sigmoid (aa=0) or tanh (aa=1), branchless
__device__ __forceinline__ float gact(float d, float aa) {
    const float bb = fmaf(-3.0f, aa, 1.0f);
    const float kk = LOG2E * fmaf(3.0f, aa, -1.0f);
    return fmaf(bb, rcpf(1.0f + ex2f(kk * d)), aa);
}

// one 100-col row dot, 3-deep pipelined LDS.128, 2 accumulators, gx in acc init
__device__ __forceinline__ float dotsingle(const ull (&w)[50], unsigned hb, float gx) {
    ull bx[3], by[3];
#pragma unroll
    for (int m = 0; m < 3; ++m)
        asm volatile("ld.shared.v2.b64 {%0,%1},[%2];"
                     : "=l"(bx[m]), "=l"(by[m]) : "r"(hb + 16u * m));
    ull a0, a1 = 0ull;
    asm("mov.b64 %0,{%1,%2};" : "=l"(a0) : "f"(gx), "f"(0.0f));
#pragma unroll
    for (int m = 0; m < 25; ++m) {
        const int sl = m % 3;
        a0 = fma2(w[2 * m],     bx[sl], a0);
        a1 = fma2(w[2 * m + 1], by[sl], a1);
        if (m + 3 < 25)
            asm volatile("ld.shared.v2.b64 {%0,%1},[%2];"
                         : "=l"(bx[sl]), "=l"(by[sl]) : "r"(hb + 16u * (m + 3)));
    }
    return hsum2(add2(a0, a1));
}

// half-row dot from shared weights (w11 lanes): 13 iters, 26 FFMA2
__device__ __forceinline__ float dot_half(const float2* __restrict__ wq,
                                          const float* __restrict__ hbase) {
    ull a0 = 0ull, a1 = 0ull;
    const ulonglong2* wp = (const ulonglong2*)wq;
    const ulonglong2* hp = (const ulonglong2*)hbase;
#pragma unroll
    for (int k = 0; k < 13; ++k) {
        const ulonglong2 wv = wp[k];
        const ulonglong2 hv = hp[k];
        a0 = fma2(wv.x, hv.x, a0);
        a1 = fma2(wv.y, hv.y, a1);
    }
    return hsum2(add2(a0, a1));
}

// ---------------- prep kernel ----------------
__global__ void gx_prep_kernel(const float* __restrict__ x,
                               const int*   __restrict__ y,
                               const float* __restrict__ eWih,
                               const float* __restrict__ ebih,
                               const float* __restrict__ ebhh,
                               const float* __restrict__ dWih,
                               const float* __restrict__ dbih,
                               const float* __restrict__ dbhh)
{
    int idx = blockIdx.x * blockDim.x + threadIdx.x;
    if (idx >= TENC * 400) return;
    int t = idx / 400;
    int r = idx - t * 400;
    int u = r % 100, gt = r / 100;
    int slot = (u < 96) ? (32 * (u >> 3) + ((u & 7) << 2) + gt)
                        : (384 + (u - 96) * 4 + gt);
    int dst = t * GXS + slot;
    g_gge[dst] = ebih[r] + ebhh[r]
               + x[3*t+0] * eWih[3*r+0]
               + x[3*t+1] * eWih[3*r+1]
               + x[3*t+2] * eWih[3*r+2];
    g_ggd[dst] = dbih[r] + dbhh[r] + (float)y[t] * dWih[r];
}

__device__ __forceinline__ void logits_body(
    const float* __restrict__ hRead,
    const float* __restrict__ slw, const float* __restrict__ slb,
    float* __restrict__ out, int orow, int lane)
{
    const int cls = lane & 7, piece = lane >> 3;
    float acc = 0.0f;
    const float* lp = slw + cls * HID + piece * 25;    // cls 6,7 hit zero pad
    const float* hq = hRead + piece * 25;
#pragma unroll
    for (int k = 0; k < 25; ++k)
        acc = fmaf(lp[k], hq[k], acc);
    acc += __shfl_xor_sync(0xffffffffu, acc, 8);
    acc += __shfl_xor_sync(0xffffffffu, acc, 16);
    if (piece == 0 && cls < NCLS)
        out[orow * NCLS + cls] = acc + slb[cls];
}

// fill w11's shared half-row weight table for units 96-99
__device__ __forceinline__ void fill_swq(float2 (*swq)[26],
                                         const float* __restrict__ Whh, int tid)
{
    for (int idx = tid; idx < 32 * 26; idx += NTH) {
        const int L = idx / 26, k = idx - L * 26;
        const int hf = L & 1, ri = L >> 1;
        const int u = 96 + (ri >> 2), gt = ri & 3;
        const float* row = Whh + (u + gt * HID) * HID;
        float v0 = 0.0f, v1 = 0.0f;
        if (hf == 0) {
            if (k < 24) { v0 = row[2 * k]; v1 = row[2 * k + 1]; }   // cols 0-47
        } else {
            v0 = row[48 + 2 * k]; v1 = row[49 + 2 * k];             // cols 48-99
        }
        swq[L][k] = make_float2(v0, v1);
    }
}

// one LSTM step for all 384 lanes (single call site per phase)
template<bool DEC>
__device__ __forceinline__ void step(
    int s, int TW, const float* __restrict__ gg,
    const ull (&w)[50], unsigned hbR, const float* __restrict__ hRf,
    float* __restrict__ hW,
    float& gx, float& gx2, float& c, float& c2, float aa, float aa2,
    int tid, int wid, int lane, int u,
    const float2 (*swq)[26],
    const float* __restrict__ slw, const float* __restrict__ slb,
    float* __restrict__ out)
{
    int sn = s + 1; if (sn > TW - 1) sn = TW - 1;
    const float nx = __ldg(gg + sn * GXS + tid);           // prefetch (hidden)
    float nx2 = 0.0f;
    if (wid == 11) nx2 = __ldg(gg + sn * GXS + 384 + (lane >> 1));

    const float d = dotsingle(w, hbR, gx);

    // full-row update (units 0-95)
    const float act = gact(d, aa);
    const int base = lane & ~3;
    const float iv = __shfl_sync(0xffffffffu, act, base);
    const float fv = __shfl_sync(0xffffffffu, act, base + 1);
    const float gv = __shfl_sync(0xffffffffu, act, base + 2);
    const float ov = __shfl_sync(0xffffffffu, act, base + 3);
    c = fmaf(fv, c, iv * gv);
    const float h = ov * tanhf_fast(c);
    if ((lane & 3) == 0) hW[u] = h;

    if (wid == 11) {
        // half-rows of units 96-99 (weights from shared swq)
        const int hf = lane & 1;
        float e = dot_half(swq[lane], hRf + hf * 48);
        e += __shfl_xor_sync(0xffffffffu, e, 1);
        e += gx2;
        const float act2 = gact(e, aa2);
        const int b2 = lane & ~7;                          // gates at b2+{0,2,4,6}
        const float i2 = __shfl_sync(0xffffffffu, act2, b2);
        const float f2 = __shfl_sync(0xffffffffu, act2, b2 + 2);
        const float g2 = __shfl_sync(0xffffffffu, act2, b2 + 4);
        const float o2 = __shfl_sync(0xffffffffu, act2, b2 + 6);
        c2 = fmaf(f2, c2, i2 * g2);
        const float h2 = o2 * tanhf_fast(c2);
        if ((lane & 7) == 0) hW[96 + (lane >> 3)] = h2;
        gx2 = nx2;
    } else if (DEC && wid == 10 && s >= 1) {
        logits_body(hRf, slw, slb, out, s - 1, lane);      // lagged logits
    }
    gx = nx;
}

// ---------------- persistent recurrence kernel ----------------
__global__ void __launch_bounds__(NTH, 1)
lstm_encdec_kernel(const float* __restrict__ eWhh,   // [400,100]
                   const float* __restrict__ dWhh,   // [400,100]
                   const float* __restrict__ linW,   // [6,100]
                   const float* __restrict__ linb,   // [6]
                   float* __restrict__ out)          // [TDEC,6]
{
    __shared__ __align__(1024) float hbuf[2][128];
    __shared__ __align__(16) float2 swq[32][26];     // w11 half-row weights
    __shared__ float slw[8 * HID];
    __shared__ float slb[NCLS];

    const int tid  = threadIdx.x;
    const int wid  = tid >> 5;
    const int lane = tid & 31;
    const int u    = 8 * wid + (lane >> 2);          // 0..95
    const int gt   = lane & 3;

    // ---- init ----
    if (tid < 128) { hbuf[0][tid] = 0.0f; hbuf[1][tid] = 0.0f; }
    if (tid < NCLS) { out[(TDEC - 1) * NCLS + tid] = 0.0f; slb[tid] = linb[tid]; }
    for (int i = tid; i < 8 * HID; i += NTH)
        slw[i] = (i < NCLS * HID) ? linW[i] : 0.0f;

    const float aa  = (gt == 2) ? 1.0f : 0.0f;
    const float aa2 = (((lane >> 1) & 3) == 2) ? 1.0f : 0.0f;   // w11 extra gate

    // ---- encoder weights ----
    ull w[50];
    {
        const ull* p = (const ull*)(eWhh + (u + gt * HID) * HID);
#pragma unroll
        for (int k = 0; k < 50; ++k) w[k] = p[k];
    }
    fill_swq(swq, eWhh, tid);
    float c = 0.0f, c2 = 0.0f;
    __syncthreads();

    const unsigned hb0 = (unsigned)__cvta_generic_to_shared(&hbuf[0][0]);
    const unsigned hb1 = hb0 + 512u;
    float* const h0 = &hbuf[0][0];
    float* const h1 = &hbuf[1][0];

    float gx  = __ldg(g_gge + tid);
    float gx2 = (wid == 11) ? __ldg(g_gge + 384 + (lane >> 1)) : 0.0f;

    // ================= encoder: 4096 steps (single call site) =================
#pragma unroll 1
    for (int s = 0; s < TENC; ++s) {
        const int odd = s & 1;
        step<false>(s, TENC, g_gge, w,
                    odd ? hb1 : hb0, odd ? h1 : h0, odd ? h0 : h1,
                    gx, gx2, c, c2, aa, aa2,
                    tid, wid, lane, u, swq, slw, slb, out);
        __syncthreads();
    }
    // 4096 even -> h_enc in hbuf[0]

    // ---- decoder weights ----
    {
        const ull* p = (const ull*)(dWhh + (u + gt * HID) * HID);
#pragma unroll
        for (int k = 0; k < 50; ++k) w[k] = p[k];
    }
    fill_swq(swq, dWhh, tid);                // prev barrier covers old readers
    gx  = __ldg(g_ggd + tid);
    gx2 = (wid == 11) ? __ldg(g_ggd + 384 + (lane >> 1)) : 0.0f;
    __syncthreads();                         // swq visible before first use

    // ================= decoder: 4095 work steps (single call site) =============
    const int TW = TDEC - 1;                 // 4095
#pragma unroll 1
    for (int s = 0; s < TW; ++s) {           // s = 0..4094; logits rows 0..4093 inside
        const int odd = s & 1;
        step<true>(s, TW, g_ggd, w,
                   odd ? hb1 : hb0, odd ? h1 : h0, odd ? h0 : h1,
                   gx, gx2, c, c2, aa, aa2,
                   tid, wid, lane, u, swq, slw, slb, out);
        __syncthreads();
    }
    // last step (s=4094, even) wrote h_4095 into hbuf[1]
    // final logits row 4094 from h1 (row 4095 stays zero)
    if (wid == 10) logits_body(h1, slw, slb, out, TDEC - 2, lane);
}

extern "C" void kernel_launch(void* const* d_in, const int* in_sizes, int n_in,
                              void* d_out, int out_size) {
    const float* x     = (const float*)d_in[0];
    const int*   y     = (const int*)  d_in[1];
    const float* eWih  = (const float*)d_in[2];
    const float* eWhh  = (const float*)d_in[3];
    const float* ebih  = (const float*)d_in[4];
    const float* ebhh  = (const float*)d_in[5];
    const float* dWih  = (const float*)d_in[6];
    const float* dWhh  = (const float*)d_in[7];
    const float* dbih  = (const float*)d_in[8];
    const float* dbhh  = (const float*)d_in[9];
    const float* linW  = (const float*)d_in[10];
    const float* linb  = (const float*)d_in[11];
    float* out = (float*)d_out;

    const int n = TENC * 400;
    gx_prep_kernel<<<(n + 255) / 256, 256>>>(x, y, eWih, ebih, ebhh,
                                             dWih, dbih, dbhh);
    lstm_encdec_kernel<<<1, NTH>>>(eWhh, dWhh, linW, linb, out);
}